// round 4
// baseline (speedup 1.0000x reference)
#include <cuda_runtime.h>
#include <cuda_bf16.h>
#include <cstdint>

// TopK(k=64) + sigmoid scatter over rows of [16384, 4096] fp32.
// One CTA per row. Keys held in registers (no shared key array).
// Selection: predicated 2048-bin histogram over top 11 key bits (only keys
// >= f2k(1.5), which provably contains the top-64 for N(0,1) rows), then
// compact the threshold bin's ~20 candidates and binary-search the remaining
// 21 bits on warp 0. Exact fallbacks cover arbitrary inputs.

constexpr int D    = 4096;   // row length
constexpr int T    = 256;    // threads per CTA
constexpr int KSEL = 64;     // top-k budget
constexpr int NB   = 2048;   // histogram bins (top 11 bits)
constexpr int CCAP = 256;    // candidate buffer capacity

__device__ __forceinline__ uint32_t f2k(uint32_t u) {
    // monotonic: larger float -> larger unsigned key (SHF + LOP3)
    return u ^ ((uint32_t)((int)u >> 31) | 0x80000000u);
}
__device__ __forceinline__ float k2f(uint32_t k) {
    uint32_t m = (uint32_t)((int)k >> 31);
    return __uint_as_float(k ^ (~m | 0x80000000u));
}
__device__ __forceinline__ float sigm(float f) {
    return __frcp_rn(1.0f + __expf(-f));
}

__global__ __launch_bounds__(T, 6)
void topk_sigmoid_kernel(const float* __restrict__ x,
                         float* __restrict__ out) {
    __shared__ __align__(16) int hist[NB];
    __shared__ uint32_t cand[CCAP];
    __shared__ int warpsum[8];
    __shared__ uint32_t s_bin;
    __shared__ int s_remk, s_neq, s_tot, s_n2;
    __shared__ uint32_t s_thr;
    __shared__ int s_allt, s_remk2;

    const int row  = blockIdx.x;
    const int tid  = threadIdx.x;
    const int lane = tid & 31;
    const int wrp  = tid >> 5;
    const uint4* __restrict__ x4 =
        reinterpret_cast<const uint4*>(x) + (size_t)row * (D / 4);

    // ---- zero hist (8 bins/thread, 2x STS.128) ----
    reinterpret_cast<int4*>(hist)[tid * 2]     = make_int4(0, 0, 0, 0);
    reinterpret_cast<int4*>(hist)[tid * 2 + 1] = make_int4(0, 0, 0, 0);
    if (tid == 0) s_n2 = 0;
    __syncthreads();

    // ---- load row, keys to registers, predicated top-11-bit histogram ----
    const uint32_t T0 = 0xBFC00000u;  // f2k(1.5f); bin-aligned (1534*2^21)
    uint4 k[4];
    #pragma unroll
    for (int j = 0; j < 4; ++j) {
        uint4 u = x4[tid + T * j];
        k[j].x = f2k(u.x); k[j].y = f2k(u.y);
        k[j].z = f2k(u.z); k[j].w = f2k(u.w);
        #pragma unroll
        for (int e = 0; e < 4; ++e) {
            uint32_t kk = (e == 0) ? k[j].x : (e == 1) ? k[j].y
                        : (e == 2) ? k[j].z : k[j].w;
            if (kk >= T0) atomicAdd(&hist[kk >> 21], 1);  // ~274/row, spread
        }
    }
    __syncthreads();

    // ---- all-thread bin search over hist (tid owns 8 consecutive bins) ----
    auto binsearch = [&](int remk) {
        int4 a = reinterpret_cast<const int4*>(hist)[tid * 2];
        int4 b = reinterpret_cast<const int4*>(hist)[tid * 2 + 1];
        int h[8] = {a.x, a.y, a.z, a.w, b.x, b.y, b.z, b.w};
        int t[8];
        t[7] = h[7];
        #pragma unroll
        for (int j = 6; j >= 0; --j) t[j] = h[j] + t[j + 1];
        int tot = t[0];
        int s = tot;  // inclusive suffix over lanes >= mine
        #pragma unroll
        for (int o = 1; o < 32; o <<= 1) {
            int v = __shfl_down_sync(0xFFFFFFFFu, s, o);
            if (lane + o < 32) s += v;
        }
        if (lane == 0) warpsum[wrp] = s;
        __syncthreads();
        int above = 0, tot_all = 0;
        #pragma unroll
        for (int w = 0; w < 8; ++w) {
            int ws = warpsum[w];
            tot_all += ws;
            if (w > wrp) above += ws;
        }
        if (tid == 0) s_tot = tot_all;
        int G0 = above + (s - tot);  // bins above this thread's group
        #pragma unroll
        for (int j = 0; j < 8; ++j) {
            int G = G0 + t[j] - h[j];  // strictly above bin (tid,j)
            if (G < remk && G + h[j] >= remk) {  // exactly one bin matches
                s_bin  = (uint32_t)(tid * 8 + j);
                s_remk = remk - G;
                s_neq  = h[j];
            }
        }
    };

    binsearch(KSEL);
    __syncthreads();

    if (s_tot < KSEL) {
        // rare exact fallback: rebuild full (unpredicated) histogram
        __syncthreads();
        reinterpret_cast<int4*>(hist)[tid * 2]     = make_int4(0, 0, 0, 0);
        reinterpret_cast<int4*>(hist)[tid * 2 + 1] = make_int4(0, 0, 0, 0);
        __syncthreads();
        #pragma unroll
        for (int j = 0; j < 4; ++j) {
            #pragma unroll
            for (int e = 0; e < 4; ++e) {
                uint32_t kk = (e == 0) ? k[j].x : (e == 1) ? k[j].y
                            : (e == 2) ? k[j].z : k[j].w;
                atomicAdd(&hist[kk >> 21], 1);
            }
        }
        __syncthreads();
        binsearch(KSEL);
        __syncthreads();
    }

    uint32_t prefix = s_bin;  // unshifted high-bits value
    int remk = s_remk;
    int neq  = s_neq;
    int shift = 21;           // keys match prefix on bits [shift, 32)

    // ---- rare refinement levels if the bin is huge (ties) ----
    while (neq != remk && neq > CCAP && shift > 0) {
        int w  = (shift >= 11) ? 11 : shift;
        int ns = shift - w;
        reinterpret_cast<int4*>(hist)[tid * 2]     = make_int4(0, 0, 0, 0);
        reinterpret_cast<int4*>(hist)[tid * 2 + 1] = make_int4(0, 0, 0, 0);
        __syncthreads();
        #pragma unroll
        for (int j = 0; j < 4; ++j) {
            #pragma unroll
            for (int e = 0; e < 4; ++e) {
                uint32_t kk = (e == 0) ? k[j].x : (e == 1) ? k[j].y
                            : (e == 2) ? k[j].z : k[j].w;
                if ((kk >> shift) == prefix)
                    atomicAdd(&hist[(kk >> ns) & ((1u << w) - 1u)], 1);
            }
        }
        __syncthreads();
        binsearch(remk);
        __syncthreads();
        prefix = (prefix << w) | s_bin;
        remk = s_remk;
        neq  = s_neq;
        shift = ns;
        __syncthreads();
    }

    uint32_t thr;
    bool allt;
    int remk2;
    if (neq == remk) {
        // whole remaining range included
        thr = prefix << shift;
        allt = true;
        remk2 = remk;
    } else if (neq <= CCAP) {
        // ---- compact the ~neq candidates, warp0 binary-search low bits ----
        #pragma unroll
        for (int j = 0; j < 4; ++j) {
            #pragma unroll
            for (int e = 0; e < 4; ++e) {
                uint32_t kk = (e == 0) ? k[j].x : (e == 1) ? k[j].y
                            : (e == 2) ? k[j].z : k[j].w;
                if ((kk >> shift) == prefix)
                    cand[atomicAdd(&s_n2, 1)] = kk;
            }
        }
        __syncthreads();
        if (wrp == 0) {
            int h2 = s_n2;  // == neq
            uint32_t cr[8];
            bool cv[8];
            #pragma unroll
            for (int i = 0; i < 8; ++i) {
                int ix = lane + 32 * i;
                cv[i] = (ix < h2);
                cr[i] = cv[i] ? cand[ix] : 0u;
            }
            uint32_t t = prefix << shift;
            for (int bit = shift - 1; bit >= 0; --bit) {
                uint32_t t2 = t | (1u << bit);
                int c = 0;
                #pragma unroll
                for (int i = 0; i < 8; ++i) c += (cv[i] && cr[i] >= t2);
                c = __reduce_add_sync(0xFFFFFFFFu, c);
                if (c >= remk) t = t2;
            }
            int cg = 0, ce = 0;
            #pragma unroll
            for (int i = 0; i < 8; ++i) {
                cg += (cv[i] && cr[i] > t);
                ce += (cv[i] && cr[i] == t);
            }
            cg = __reduce_add_sync(0xFFFFFFFFu, cg);
            ce = __reduce_add_sync(0xFFFFFFFFu, ce);
            if (lane == 0) {
                s_thr   = t;
                s_remk2 = remk - cg;
                s_allt  = (ce == remk - cg);
            }
        }
        __syncthreads();
        thr   = s_thr;
        allt  = (s_allt != 0);
        remk2 = s_remk2;
    } else {
        // shift == 0 and still oversized: thr fully determined, ties remain
        thr = prefix;
        allt = false;
        remk2 = remk;
    }

    // ---- output: sigmoid for selected, 0 otherwise (128-bit coalesced) ----
    float* __restrict__ orow = out + (size_t)row * D;
    #pragma unroll
    for (int j = 0; j < 4; ++j) {
        float4 r;
        #pragma unroll
        for (int e = 0; e < 4; ++e) {
            uint32_t kk = (e == 0) ? k[j].x : (e == 1) ? k[j].y
                        : (e == 2) ? k[j].z : k[j].w;
            float f = 0.0f;
            if (kk >= thr) {                 // ~64/4096 elements
                bool inc = (kk > thr) || allt;
                if (!inc) {                  // exact tie-break, ~never taken
                    int idx = 4 * (tid + T * j) + e;
                    const float* xr = x + (size_t)row * D;
                    int rk = 0;
                    for (int q = 0; q < idx; ++q)
                        rk += (f2k(__float_as_uint(xr[q])) == thr);
                    inc = (rk < remk2);      // lowest-index ties first
                }
                if (inc) f = sigm(k2f(kk));
            }
            ((float*)&r)[e] = f;
        }
        reinterpret_cast<float4*>(orow)[tid + T * j] = r;
    }
}

extern "C" void kernel_launch(void* const* d_in, const int* in_sizes, int n_in,
                              void* d_out, int out_size) {
    const float* x = (const float*)d_in[0];
    float* out = (float*)d_out;
    int rows = in_sizes[0] / D;
    topk_sigmoid_kernel<<<rows, T>>>(x, out);
}

// round 5
// speedup vs baseline: 1.2128x; 1.2128x over previous
#include <cuda_runtime.h>
#include <cuda_bf16.h>
#include <cstdint>

// TopK(k=64) + sigmoid scatter over rows of [16384, 4096] fp32.
// One CTA per row, keys staged in shared. Selection: predicated 2048-bin
// histogram over top-11 key bits (only keys >= f2k(1.5) — provably contains
// the top-64 for N(0,1) rows, exact fallback otherwise), then compact the
// threshold bin's ~20 candidates and warp0-binary-search the low 21 bits.

constexpr int D    = 4096;
constexpr int T    = 256;
constexpr int KSEL = 64;
constexpr int NB   = 2048;   // bins = top 11 key bits
constexpr int CCAP = 256;    // candidate buffer capacity

__device__ __forceinline__ uint32_t f2k(uint32_t u) {
    return u ^ ((uint32_t)((int)u >> 31) | 0x80000000u);  // monotonic key
}
__device__ __forceinline__ float k2f(uint32_t k) {
    uint32_t m = (uint32_t)((int)k >> 31);
    return __uint_as_float(k ^ (~m | 0x80000000u));
}
__device__ __forceinline__ float sigm(float f) {
    return __frcp_rn(1.0f + __expf(-f));
}

__global__ __launch_bounds__(T, 8)
void topk_sigmoid_kernel(const float* __restrict__ x,
                         float* __restrict__ out) {
    __shared__ __align__(16) uint32_t skey[D];
    __shared__ __align__(16) int hist[NB];
    __shared__ uint32_t cand[CCAP];
    __shared__ int warpsum[8];
    __shared__ uint32_t s_bin;
    __shared__ int s_remk, s_neq, s_tot, s_n2;
    __shared__ uint32_t s_thr;
    __shared__ int s_allt, s_remk2;

    const int row  = blockIdx.x;
    const int tid  = threadIdx.x;
    const int lane = tid & 31;
    const int wrp  = tid >> 5;
    const uint4* __restrict__ x4 =
        reinterpret_cast<const uint4*>(x) + (size_t)row * (D / 4);

    // ---- zero hist (8 bins/thread) ----
    reinterpret_cast<int4*>(hist)[tid * 2]     = make_int4(0, 0, 0, 0);
    reinterpret_cast<int4*>(hist)[tid * 2 + 1] = make_int4(0, 0, 0, 0);
    if (tid == 0) s_n2 = 0;
    __syncthreads();

    // ---- load, convert, stage keys, predicated top-11-bit histogram ----
    const uint32_t T0 = 0xBFC00000u;  // f2k(1.5f); == 1534 << 21 (bin-aligned)
    #pragma unroll
    for (int j = 0; j < 4; ++j) {
        int v = tid + T * j;
        uint4 u = x4[v];
        uint4 kk;
        kk.x = f2k(u.x); kk.y = f2k(u.y); kk.z = f2k(u.z); kk.w = f2k(u.w);
        reinterpret_cast<uint4*>(skey)[v] = kk;
        if (kk.x >= T0) atomicAdd(&hist[kk.x >> 21], 1);
        if (kk.y >= T0) atomicAdd(&hist[kk.y >> 21], 1);
        if (kk.z >= T0) atomicAdd(&hist[kk.z >> 21], 1);
        if (kk.w >= T0) atomicAdd(&hist[kk.w >> 21], 1);
    }
    __syncthreads();

    // ---- all-thread bin search over hist[NB]; tid owns 8 consecutive bins ----
    auto binsearch = [&](int remk) {
        int4 a = reinterpret_cast<const int4*>(hist)[tid * 2];
        int4 b = reinterpret_cast<const int4*>(hist)[tid * 2 + 1];
        int h[8] = {a.x, a.y, a.z, a.w, b.x, b.y, b.z, b.w};
        int t[8];
        t[7] = h[7];
        #pragma unroll
        for (int j = 6; j >= 0; --j) t[j] = h[j] + t[j + 1];
        int tot = t[0];
        int s = tot;  // inclusive suffix over lanes >= mine
        #pragma unroll
        for (int o = 1; o < 32; o <<= 1) {
            int v = __shfl_down_sync(0xFFFFFFFFu, s, o);
            if (lane + o < 32) s += v;
        }
        if (lane == 0) warpsum[wrp] = s;
        __syncthreads();
        int above = 0, tot_all = 0;
        #pragma unroll
        for (int w = 0; w < 8; ++w) {
            int ws = warpsum[w];
            tot_all += ws;
            if (w > wrp) above += ws;
        }
        if (tid == 0) s_tot = tot_all;
        int G0 = above + (s - tot);
        #pragma unroll
        for (int j = 0; j < 8; ++j) {
            int G = G0 + t[j] - h[j];            // count strictly above bin
            if (G < remk && G + h[j] >= remk) {  // exactly one bin matches
                s_bin  = (uint32_t)(tid * 8 + j);
                s_remk = remk - G;
                s_neq  = h[j];
            }
        }
    };

    binsearch(KSEL);
    __syncthreads();

    if (s_tot < KSEL) {
        // exact fallback (~never for N(0,1)): full unpredicated histogram
        __syncthreads();
        reinterpret_cast<int4*>(hist)[tid * 2]     = make_int4(0, 0, 0, 0);
        reinterpret_cast<int4*>(hist)[tid * 2 + 1] = make_int4(0, 0, 0, 0);
        __syncthreads();
        #pragma unroll
        for (int j = 0; j < 4; ++j) {
            uint4 kk = reinterpret_cast<const uint4*>(skey)[tid + T * j];
            atomicAdd(&hist[kk.x >> 21], 1);
            atomicAdd(&hist[kk.y >> 21], 1);
            atomicAdd(&hist[kk.z >> 21], 1);
            atomicAdd(&hist[kk.w >> 21], 1);
        }
        __syncthreads();
        binsearch(KSEL);
        __syncthreads();
    }

    uint32_t prefix = s_bin;  // high bits [shift,32) of the threshold
    int remk = s_remk;
    int neq  = s_neq;
    int shift = 21;

    // ---- rare refinement if bin oversized (massive ties) ----
    while (neq != remk && neq > CCAP && shift > 0) {
        int w  = (shift >= 11) ? 11 : shift;
        int ns = shift - w;
        reinterpret_cast<int4*>(hist)[tid * 2]     = make_int4(0, 0, 0, 0);
        reinterpret_cast<int4*>(hist)[tid * 2 + 1] = make_int4(0, 0, 0, 0);
        __syncthreads();
        #pragma unroll
        for (int j = 0; j < 4; ++j) {
            uint4 k4 = reinterpret_cast<const uint4*>(skey)[tid + T * j];
            #pragma unroll
            for (int e = 0; e < 4; ++e) {
                uint32_t kk = (e == 0) ? k4.x : (e == 1) ? k4.y
                            : (e == 2) ? k4.z : k4.w;
                if ((kk >> shift) == prefix)
                    atomicAdd(&hist[(kk >> ns) & ((1u << w) - 1u)], 1);
            }
        }
        __syncthreads();
        binsearch(remk);
        __syncthreads();
        prefix = (prefix << w) | s_bin;
        remk = s_remk;
        neq  = s_neq;
        shift = ns;
        __syncthreads();
    }

    uint32_t thr;
    bool allt;
    int remk2;
    if (neq == remk) {
        thr = prefix << shift;   // whole remaining range included
        allt = true;
        remk2 = remk;
    } else if (neq <= CCAP) {
        // ---- compact ~neq candidates from skey, warp0 resolves low bits ----
        #pragma unroll
        for (int j = 0; j < 4; ++j) {
            uint4 k4 = reinterpret_cast<const uint4*>(skey)[tid + T * j];
            #pragma unroll
            for (int e = 0; e < 4; ++e) {
                uint32_t kk = (e == 0) ? k4.x : (e == 1) ? k4.y
                            : (e == 2) ? k4.z : k4.w;
                if ((kk >> shift) == prefix)
                    cand[atomicAdd(&s_n2, 1)] = kk;
            }
        }
        __syncthreads();
        if (wrp == 0) {
            int h2 = s_n2;  // == neq
            uint32_t cr[8];
            bool cv[8];
            #pragma unroll
            for (int i = 0; i < 8; ++i) {
                int ix = lane + 32 * i;
                cv[i] = (ix < h2);
                cr[i] = cv[i] ? cand[ix] : 0u;
            }
            uint32_t t = prefix << shift;
            for (int bit = shift - 1; bit >= 0; --bit) {
                uint32_t t2 = t | (1u << bit);
                int c = 0;
                #pragma unroll
                for (int i = 0; i < 8; ++i) c += (cv[i] && cr[i] >= t2);
                c = __reduce_add_sync(0xFFFFFFFFu, c);
                if (c >= remk) t = t2;
            }
            int cg = 0, ce = 0;
            #pragma unroll
            for (int i = 0; i < 8; ++i) {
                cg += (cv[i] && cr[i] > t);
                ce += (cv[i] && cr[i] == t);
            }
            cg = __reduce_add_sync(0xFFFFFFFFu, cg);
            ce = __reduce_add_sync(0xFFFFFFFFu, ce);
            if (lane == 0) {
                s_thr   = t;
                s_remk2 = remk - cg;
                s_allt  = (ce == remk - cg);
            }
        }
        __syncthreads();
        thr   = s_thr;
        allt  = (s_allt != 0);
        remk2 = s_remk2;
    } else {
        thr = prefix;            // shift==0 oversize: ties remain at thr
        allt = false;
        remk2 = remk;
    }

    // ---- output: sigmoid for selected, 0 otherwise (128-bit coalesced) ----
    float* __restrict__ orow = out + (size_t)row * D;
    #pragma unroll
    for (int j = 0; j < 4; ++j) {
        int v = tid + T * j;
        uint4 k4 = reinterpret_cast<const uint4*>(skey)[v];
        float4 r;
        #pragma unroll
        for (int e = 0; e < 4; ++e) {
            uint32_t kk = (e == 0) ? k4.x : (e == 1) ? k4.y
                        : (e == 2) ? k4.z : k4.w;
            float f = 0.0f;
            if (kk >= thr) {                 // ~64/4096 elements
                bool inc = (kk > thr) || allt;
                if (!inc) {                  // exact tie-break, ~never taken
                    int idx = 4 * v + e;
                    int rk = 0;
                    for (int q = 0; q < idx; ++q) rk += (skey[q] == thr);
                    inc = (rk < remk2);      // lowest-index ties first
                }
                if (inc) f = sigm(k2f(kk));
            }
            ((float*)&r)[e] = f;
        }
        reinterpret_cast<float4*>(orow)[v] = r;
    }
}

extern "C" void kernel_launch(void* const* d_in, const int* in_sizes, int n_in,
                              void* d_out, int out_size) {
    const float* x = (const float*)d_in[0];
    float* out = (float*)d_out;
    int rows = in_sizes[0] / D;
    topk_sigmoid_kernel<<<rows, T>>>(x, out);
}